// round 10
// baseline (speedup 1.0000x reference)
#include <cuda_runtime.h>
#include <cuda_fp16.h>
#include <math.h>

#define NN 50000        // num nodes
#define DD 128          // embedding dim (= hidden dim)
#define BB 4            // num bases
#define EE 320000       // num edges
#define BH 512          // BB * DD

// ---------------- static scratch ----------------
__device__ float  g_x[NN * DD];          // node features, 25.6 MB
__device__ __half g_hb_h[NN * BH];       // per-base projections (fp16), 51.2 MB
__device__ __half g_msg[(size_t)EE * DD];// dst-sorted messages (fp16), 81.9 MB
__device__ int    g_deg[NN];
__device__ int    g_off[NN + 1];         // CSR row offsets (by dst)
__device__ int    g_cur[NN];             // fill cursors
__device__ int    g_pos[EE];             // edge -> slot in dst-sorted order
__device__ double g_acc[3];              // loss_pos, loss_neg, auc_count

// ---------------- degree histogram ----------------
__global__ void k_zero_deg() {
    int i = blockIdx.x * blockDim.x + threadIdx.x;
    if (i < NN) g_deg[i] = 0;
}
__global__ void k_count_deg(const int* __restrict__ dst) {
    int e = blockIdx.x * blockDim.x + threadIdx.x;
    if (e < EE) atomicAdd(&g_deg[dst[e]], 1);
}

// ---------------- single-block prefix scan over degrees -> offsets ----------------
#define SCAN_T 1024
#define SCAN_CH 49          // ceil(50000 / 1024)
__global__ __launch_bounds__(SCAN_T) void k_scan() {
    __shared__ int sh[SCAN_T];
    int t = threadIdx.x;
    int base = t * SCAN_CH;
    int loc[SCAN_CH];
    int s = 0;
#pragma unroll
    for (int j = 0; j < SCAN_CH; j++) {
        int idx = base + j;
        loc[j] = s;
        if (idx < NN) s += g_deg[idx];
    }
    sh[t] = s;
    __syncthreads();
    for (int off = 1; off < SCAN_T; off <<= 1) {
        int v = (t >= off) ? sh[t - off] : 0;
        __syncthreads();
        sh[t] += v;
        __syncthreads();
    }
    int pre = (t == 0) ? 0 : sh[t - 1];
#pragma unroll
    for (int j = 0; j < SCAN_CH; j++) {
        int idx = base + j;
        if (idx < NN) {
            int o = pre + loc[j];
            g_off[idx] = o;
            g_cur[idx] = o;
        }
    }
    if (t == SCAN_T - 1) g_off[NN] = sh[t];
}

// ---------------- record each edge's slot in dst-sorted order ----------------
__global__ void k_fill(const int* __restrict__ dst) {
    int e = blockIdx.x * blockDim.x + threadIdx.x;
    if (e < EE) g_pos[e] = atomicAdd(&g_cur[dst[e]], 1);
}

// ---------------- x0 = relu(emb + bias) (float4) ----------------
__global__ void k_x0(const float* __restrict__ emb, const float* __restrict__ eb) {
    int i = blockIdx.x * blockDim.x + threadIdx.x;
    if (i < NN * DD / 4) {
        float4 v = *(const float4*)&emb[i * 4];
        float4 bsv = *(const float4*)&eb[(i & 31) * 4];
        v.x = fmaxf(v.x + bsv.x, 0.f);
        v.y = fmaxf(v.y + bsv.y, 0.f);
        v.z = fmaxf(v.z + bsv.z, 0.f);
        v.w = fmaxf(v.w + bsv.w, 0.f);
        *(float4*)&g_x[i * 4] = v;
    }
}

// ---------------- tf32 helpers ----------------
__device__ __forceinline__ unsigned f2tf32(float f) {
    unsigned u;
    asm("cvt.rna.tf32.f32 %0, %1;" : "=r"(u) : "f"(f));
    return u;
}
__device__ __forceinline__ void mma_tf32(float c[4], const unsigned a[4], const unsigned b[2]) {
    asm volatile(
        "mma.sync.aligned.m16n8k8.row.col.f32.tf32.tf32.f32 "
        "{%0,%1,%2,%3}, {%4,%5,%6,%7}, {%8,%9}, {%0,%1,%2,%3};\n"
        : "+f"(c[0]), "+f"(c[1]), "+f"(c[2]), "+f"(c[3])
        : "r"(a[0]), "r"(a[1]), "r"(a[2]), "r"(a[3]), "r"(b[0]), "r"(b[1]));
}

// ---------------- tf32 GEMM: g_hb_h[N,512] = g_x[N,128] @ bases[b] (per-basis) ----------------
__global__ __launch_bounds__(256, 2) void k_gemm_mma(const float* __restrict__ bases) {
    __shared__ unsigned Xs[128][36];
    __shared__ unsigned Ws[32][136];

    const int b  = blockIdx.x;
    const int bm = blockIdx.y * 128;
    const int tid = threadIdx.x;
    const int lane = tid & 31;
    const int wid = tid >> 5;
    const int wm = wid & 3;
    const int wn = wid >> 2;
    const int gid = lane >> 2;
    const int tig = lane & 3;

    float c[2][8][4];
#pragma unroll
    for (int mt = 0; mt < 2; mt++)
#pragma unroll
        for (int nt = 0; nt < 8; nt++)
#pragma unroll
            for (int i = 0; i < 4; i++) c[mt][nt][i] = 0.f;

#pragma unroll
    for (int kc = 0; kc < 4; kc++) {
#pragma unroll
        for (int it = 0; it < 4; it++) {
            int idx = it * 256 + tid;
            int r = idx >> 3, c4 = idx & 7;
            float4 a = make_float4(0.f, 0.f, 0.f, 0.f);
            int grow = bm + r;
            if (grow < NN) a = *(const float4*)&g_x[grow * DD + kc * 32 + c4 * 4];
            uint4 u;
            u.x = f2tf32(a.x); u.y = f2tf32(a.y); u.z = f2tf32(a.z); u.w = f2tf32(a.w);
            *(uint4*)&Xs[r][c4 * 4] = u;
        }
#pragma unroll
        for (int it = 0; it < 4; it++) {
            int idx = it * 256 + tid;
            int r = idx >> 5, c4 = idx & 31;
            float4 a = *(const float4*)&bases[(b * DD + kc * 32 + r) * DD + c4 * 4];
            uint4 u;
            u.x = f2tf32(a.x); u.y = f2tf32(a.y); u.z = f2tf32(a.z); u.w = f2tf32(a.w);
            *(uint4*)&Ws[r][c4 * 4] = u;
        }
        __syncthreads();

#pragma unroll
        for (int ks = 0; ks < 4; ks++) {
            const int k0 = ks * 8 + tig;
            const int k1 = k0 + 4;
            unsigned a[2][4], bf[8][2];
#pragma unroll
            for (int mt = 0; mt < 2; mt++) {
                int mr = wm * 32 + mt * 16 + gid;
                a[mt][0] = Xs[mr][k0];
                a[mt][1] = Xs[mr + 8][k0];
                a[mt][2] = Xs[mr][k1];
                a[mt][3] = Xs[mr + 8][k1];
            }
#pragma unroll
            for (int nt = 0; nt < 8; nt++) {
                int nc = wn * 64 + nt * 8 + gid;
                bf[nt][0] = Ws[k0][nc];
                bf[nt][1] = Ws[k1][nc];
            }
#pragma unroll
            for (int mt = 0; mt < 2; mt++)
#pragma unroll
                for (int nt = 0; nt < 8; nt++)
                    mma_tf32(c[mt][nt], a[mt], bf[nt]);
        }
        __syncthreads();
    }

#pragma unroll
    for (int mt = 0; mt < 2; mt++) {
        int row0 = bm + wm * 32 + mt * 16 + gid;
        int row1 = row0 + 8;
#pragma unroll
        for (int nt = 0; nt < 8; nt++) {
            int col = b * 128 + wn * 64 + nt * 8 + 2 * tig;
            if (row0 < NN)
                *(__half2*)&g_hb_h[row0 * BH + col] = __floats2half2_rn(c[mt][nt][0], c[mt][nt][1]);
            if (row1 < NN)
                *(__half2*)&g_hb_h[row1 * BH + col] = __floats2half2_rn(c[mt][nt][2], c[mt][nt][3]);
        }
    }
}

// ---------------- phase A: per-edge message -> msg_buf[pos[e]] (warp per edge, no atomics) ----------------
__global__ __launch_bounds__(256) void k_msg(const int* __restrict__ src,
                                             const int* __restrict__ et,
                                             const float* __restrict__ comp) {
    int e = (blockIdx.x * blockDim.x + threadIdx.x) >> 5;
    int lane = threadIdx.x & 31;
    if (e >= EE) return;
    int s = src[e], t = et[e], pos = g_pos[e];
    float c0 = __ldg(&comp[t * BB + 0]);
    float c1 = __ldg(&comp[t * BB + 1]);
    float c2 = __ldg(&comp[t * BB + 2]);
    float c3 = __ldg(&comp[t * BB + 3]);
    const uint2* hb = (const uint2*)&g_hb_h[(size_t)s * BH];
    uint2 u0 = hb[lane];
    uint2 u1 = hb[32 + lane];
    uint2 u2 = hb[64 + lane];
    uint2 u3 = hb[96 + lane];
    float2 a0 = __half22float2(*(const __half2*)&u0.x);
    float2 b0 = __half22float2(*(const __half2*)&u0.y);
    float2 a1 = __half22float2(*(const __half2*)&u1.x);
    float2 b1 = __half22float2(*(const __half2*)&u1.y);
    float2 a2 = __half22float2(*(const __half2*)&u2.x);
    float2 b2 = __half22float2(*(const __half2*)&u2.y);
    float2 a3 = __half22float2(*(const __half2*)&u3.x);
    float2 b3 = __half22float2(*(const __half2*)&u3.y);
    float4 m;
    m.x = c0 * a0.x + c1 * a1.x + c2 * a2.x + c3 * a3.x;
    m.y = c0 * a0.y + c1 * a1.y + c2 * a2.y + c3 * a3.y;
    m.z = c0 * b0.x + c1 * b1.x + c2 * b2.x + c3 * b3.x;
    m.w = c0 * b0.y + c1 * b1.y + c2 * b2.y + c3 * b3.y;
    __half2 h01 = __floats2half2_rn(m.x, m.y);
    __half2 h23 = __floats2half2_rn(m.z, m.w);
    uint2 packed;
    packed.x = *(const unsigned*)&h01;
    packed.y = *(const unsigned*)&h23;
    ((uint2*)&g_msg[(size_t)pos * DD])[lane] = packed;
}

// ---------------- phase B: contiguous segment-sum (warp per node, no atomics) ----------------
__global__ __launch_bounds__(256) void k_segsum(const float* __restrict__ bias,
                                                int do_relu) {
    int n = (blockIdx.x * blockDim.x + threadIdx.x) >> 5;
    int lane = threadIdx.x & 31;
    if (n >= NN) return;
    int beg = g_off[n], end = g_off[n + 1];
    float4 acc = make_float4(0.f, 0.f, 0.f, 0.f);
    const uint2* mb = (const uint2*)g_msg;
    for (int i = beg; i < end; i++) {
        uint2 u = mb[(size_t)i * 32 + lane];         // contiguous, index-free
        float2 f01 = __half22float2(*(const __half2*)&u.x);
        float2 f23 = __half22float2(*(const __half2*)&u.y);
        acc.x += f01.x;
        acc.y += f01.y;
        acc.z += f23.x;
        acc.w += f23.y;
    }
    float inv = 1.0f / fmaxf((float)(end - beg), 1.0f);
    float4 bsv = *(const float4*)&bias[lane * 4];
    acc.x = acc.x * inv + bsv.x;
    acc.y = acc.y * inv + bsv.y;
    acc.z = acc.z * inv + bsv.z;
    acc.w = acc.w * inv + bsv.w;
    if (do_relu) {
        acc.x = fmaxf(acc.x, 0.f); acc.y = fmaxf(acc.y, 0.f);
        acc.z = fmaxf(acc.z, 0.f); acc.w = fmaxf(acc.w, 0.f);
    }
    *(float4*)&g_x[n * DD + lane * 4] = acc;
}

// ---------------- decode ----------------
__global__ void k_zero_acc() {
    int i = threadIdx.x;
    if (i < 3) g_acc[i] = 0.0;
}

__device__ __forceinline__ float softplusf(float x) {
    return fmaxf(x, 0.f) + log1pf(expf(-fabsf(x)));
}

__global__ __launch_bounds__(256) void k_decode(const int* __restrict__ hh,
                                                const int* __restrict__ tt,
                                                const int* __restrict__ et,
                                                const int* __restrict__ ng,
                                                const float* __restrict__ rel,
                                                float* __restrict__ out) {
    __shared__ float s_lp[8], s_ln[8], s_au[8];
    int w = (blockIdx.x * blockDim.x + threadIdx.x) >> 5;
    int lane = threadIdx.x & 31;
    int wid = threadIdx.x >> 5;
    float lp = 0.f, ln = 0.f, au = 0.f;
    if (w < EE) {
        int a = hh[w], b = tt[w], c = ng[w], r = et[w];
        float4 xh = *(const float4*)&g_x[a * DD + lane * 4];
        float4 xt = *(const float4*)&g_x[b * DD + lane * 4];
        float4 xn = *(const float4*)&g_x[c * DD + lane * 4];
        float4 re = *(const float4*)&rel[r * DD + lane * 4];
        float hx = xh.x * re.x, hy = xh.y * re.y, hz = xh.z * re.z, hw = xh.w * re.w;
        float p = hx * xt.x + hy * xt.y + hz * xt.z + hw * xt.w;
        float q = hx * xn.x + hy * xn.y + hz * xn.z + hw * xn.w;
#pragma unroll
        for (int o = 16; o; o >>= 1) {
            p += __shfl_xor_sync(0xFFFFFFFFu, p, o);
            q += __shfl_xor_sync(0xFFFFFFFFu, q, o);
        }
        if (lane == 0) {
            out[w] = p;
            lp = softplusf(-p);
            ln = softplusf(q);
            au = (p > q) ? 1.f : 0.f;
        }
    }
    if (lane == 0) { s_lp[wid] = lp; s_ln[wid] = ln; s_au[wid] = au; }
    __syncthreads();
    if (threadIdx.x == 0) {
        double A = 0, Bd = 0, C = 0;
#pragma unroll
        for (int k = 0; k < 8; k++) { A += s_lp[k]; Bd += s_ln[k]; C += s_au[k]; }
        atomicAdd(&g_acc[0], A);
        atomicAdd(&g_acc[1], Bd);
        atomicAdd(&g_acc[2], C);
    }
}

__global__ void k_final(float* __restrict__ out, int out_size) {
    if (blockIdx.x == 0 && threadIdx.x == 0) {
        double inv = 1.0 / (double)EE;
        if (out_size >= EE + 1) out[EE] = (float)(0.5 * (g_acc[0] + g_acc[1]) * inv);
        if (out_size >= EE + 2) out[EE + 1] = (float)(g_acc[2] * inv);
    }
}

// ---------------- launch ----------------
extern "C" void kernel_launch(void* const* d_in, const int* in_sizes, int n_in,
                              void* d_out, int out_size) {
    const float* emb    = (const float*)d_in[0];
    const float* ebias  = (const float*)d_in[1];
    const float* bases1 = (const float*)d_in[2];
    const float* comp1  = (const float*)d_in[3];
    const float* bias1  = (const float*)d_in[4];
    const float* bases2 = (const float*)d_in[5];
    const float* comp2  = (const float*)d_in[6];
    const float* bias2  = (const float*)d_in[7];
    const float* rel    = (const float*)d_in[8];
    const int*   eidx   = (const int*)d_in[9];
    const int*   etype  = (const int*)d_in[10];
    const int*   negt   = (const int*)d_in[11];
    const int* src = eidx;
    const int* dst = eidx + EE;
    float* out = (float*)d_out;

    // CSR build (by dst) + x0
    k_zero_deg<<<(NN + 255) / 256, 256>>>();
    k_count_deg<<<(EE + 255) / 256, 256>>>(dst);
    k_scan<<<1, SCAN_T>>>();
    k_fill<<<(EE + 255) / 256, 256>>>(dst);
    k_x0<<<(NN * DD / 4 + 255) / 256, 256>>>(emb, ebias);

    dim3 ggrid(BB, (NN + 127) / 128);   // (4, 391); blockIdx.x = basis
    int seg_blocks = (NN * 32 + 255) / 256;

    // ---- layer 1 ----
    k_gemm_mma<<<ggrid, 256>>>(bases1);
    k_msg<<<EE / 8, 256>>>(src, etype, comp1);
    k_segsum<<<seg_blocks, 256>>>(bias1, 1);

    // ---- layer 2 ----
    k_gemm_mma<<<ggrid, 256>>>(bases2);
    k_msg<<<EE / 8, 256>>>(src, etype, comp2);
    k_segsum<<<seg_blocks, 256>>>(bias2, 0);

    // ---- decode ----
    k_zero_acc<<<1, 32>>>();
    k_decode<<<EE / 8, 256>>>(src, dst, etype, negt, rel, out);
    k_final<<<1, 32>>>(out, out_size);
}

// round 11
// speedup vs baseline: 1.1311x; 1.1311x over previous
#include <cuda_runtime.h>
#include <cuda_fp16.h>
#include <math.h>

#define NN 50000        // num nodes
#define DD 128          // embedding dim (= hidden dim)
#define BB 4            // num bases
#define EE 320000       // num edges
#define BH 512          // BB * DD

// ---------------- static scratch ----------------
__device__ float  g_x[NN * DD];          // node features, 25.6 MB
__device__ __half g_hb_h[NN * BH];       // per-base projections (fp16), 51.2 MB
__device__ float  g_agg[NN * DD];        // scatter accumulator, 25.6 MB
__device__ __half g_Wt[2 * BB * DD * DD];// transposed bases [layer][b][n][k] fp16
__device__ int    g_deg[NN];
__device__ int    g_off[NN + 1];
__device__ int    g_cur[NN];
__device__ int    g_ssrc[EE];            // src, dst-sorted
__device__ int    g_sdst[EE];            // dst, dst-sorted
__device__ int    g_set[EE];             // edge type, dst-sorted
__device__ double g_acc[3];

// ---------------- degree histogram ----------------
__global__ void k_zero_deg() {
    int i = blockIdx.x * blockDim.x + threadIdx.x;
    if (i < NN) g_deg[i] = 0;
}
__global__ void k_count_deg(const int* __restrict__ dst) {
    int e = blockIdx.x * blockDim.x + threadIdx.x;
    if (e < EE) atomicAdd(&g_deg[dst[e]], 1);
}

// ---------------- single-block prefix scan ----------------
#define SCAN_T 1024
#define SCAN_CH 49
__global__ __launch_bounds__(SCAN_T) void k_scan() {
    __shared__ int sh[SCAN_T];
    int t = threadIdx.x;
    int base = t * SCAN_CH;
    int loc[SCAN_CH];
    int s = 0;
#pragma unroll
    for (int j = 0; j < SCAN_CH; j++) {
        int idx = base + j;
        loc[j] = s;
        if (idx < NN) s += g_deg[idx];
    }
    sh[t] = s;
    __syncthreads();
    for (int off = 1; off < SCAN_T; off <<= 1) {
        int v = (t >= off) ? sh[t - off] : 0;
        __syncthreads();
        sh[t] += v;
        __syncthreads();
    }
    int pre = (t == 0) ? 0 : sh[t - 1];
#pragma unroll
    for (int j = 0; j < SCAN_CH; j++) {
        int idx = base + j;
        if (idx < NN) {
            int o = pre + loc[j];
            g_off[idx] = o;
            g_cur[idx] = o;
        }
    }
    if (t == SCAN_T - 1) g_off[NN] = sh[t];
}

// ---------------- bucket edges by dst: write sorted src/dst/type ----------------
__global__ void k_fill(const int* __restrict__ src, const int* __restrict__ dst,
                       const int* __restrict__ et) {
    int e = blockIdx.x * blockDim.x + threadIdx.x;
    if (e < EE) {
        int d = dst[e];
        int pos = atomicAdd(&g_cur[d], 1);
        g_ssrc[pos] = src[e];
        g_sdst[pos] = d;
        g_set[pos]  = et[e];
    }
}

// ---------------- transpose bases -> g_Wt[layer][b][n][k] fp16 ----------------
__global__ void k_wt(const float* __restrict__ bases, int layer) {
    int i = blockIdx.x * blockDim.x + threadIdx.x;   // over 4*128*128
    if (i < BB * DD * DD) {
        int b = i >> 14, k = (i >> 7) & 127, n = i & 127;
        g_Wt[((layer * BB + b) * DD + n) * DD + k] = __float2half(bases[i]);
    }
}

// ---------------- x0 = relu(emb + bias), zero agg (float4) ----------------
__global__ void k_x0(const float* __restrict__ emb, const float* __restrict__ eb) {
    int i = blockIdx.x * blockDim.x + threadIdx.x;
    if (i < NN * DD / 4) {
        float4 v = *(const float4*)&emb[i * 4];
        float4 bsv = *(const float4*)&eb[(i & 31) * 4];
        v.x = fmaxf(v.x + bsv.x, 0.f);
        v.y = fmaxf(v.y + bsv.y, 0.f);
        v.z = fmaxf(v.z + bsv.z, 0.f);
        v.w = fmaxf(v.w + bsv.w, 0.f);
        *(float4*)&g_x[i * 4] = v;
        *(float4*)&g_agg[i * 4] = make_float4(0.f, 0.f, 0.f, 0.f);
    }
}

// ---------------- f16 mma helper ----------------
__device__ __forceinline__ void mma_f16(float c[4], const unsigned a[4], const unsigned b[2]) {
    asm volatile(
        "mma.sync.aligned.m16n8k16.row.col.f32.f16.f16.f32 "
        "{%0,%1,%2,%3}, {%4,%5,%6,%7}, {%8,%9}, {%0,%1,%2,%3};\n"
        : "+f"(c[0]), "+f"(c[1]), "+f"(c[2]), "+f"(c[3])
        : "r"(a[0]), "r"(a[1]), "r"(a[2]), "r"(a[3]), "r"(b[0]), "r"(b[1]));
}

// ---------------- fp16 GEMM: g_hb_h[N,512] = g_x[N,128] @ W[b] ----------------
// Block tile 128(M) x 128(N=one basis) x 32(K). m16n8k16 f16 mma, fp32 accum.
__global__ __launch_bounds__(256, 2) void k_gemm_mma(int layer) {
    __shared__ unsigned Xs[128][20];   // half2 cells [m][k/2], pad 20 -> conflict-free
    __shared__ unsigned Wst[128][20];  // half2 cells [n][k/2]

    const int b  = blockIdx.x;
    const int bm = blockIdx.y * 128;
    const int tid = threadIdx.x;
    const int lane = tid & 31;
    const int wid = tid >> 5;
    const int wm = wid & 3;            // warp row, 32 rows each
    const int wn = wid >> 2;           // warp col, 64 cols each
    const int gid = lane >> 2;         // 0..7
    const int tig = lane & 3;          // 0..3

    const __half* Wtb = &g_Wt[(layer * BB + b) * DD * DD];

    float c[2][8][4];
#pragma unroll
    for (int mt = 0; mt < 2; mt++)
#pragma unroll
        for (int nt = 0; nt < 8; nt++)
#pragma unroll
            for (int i = 0; i < 4; i++) c[mt][nt][i] = 0.f;

#pragma unroll
    for (int kc = 0; kc < 4; kc++) {
        // ---- X tile 128x32 -> half2 ----
#pragma unroll
        for (int it = 0; it < 4; it++) {
            int idx = it * 256 + tid;          // 0..1023 float4s
            int r = idx >> 3, c4 = idx & 7;
            float4 a = make_float4(0.f, 0.f, 0.f, 0.f);
            int grow = bm + r;
            if (grow < NN) a = *(const float4*)&g_x[grow * DD + kc * 32 + c4 * 4];
            __half2 h0 = __floats2half2_rn(a.x, a.y);
            __half2 h1 = __floats2half2_rn(a.z, a.w);
            Xs[r][c4 * 2 + 0] = *(const unsigned*)&h0;
            Xs[r][c4 * 2 + 1] = *(const unsigned*)&h1;
        }
        // ---- W tile: g_Wt[b][n][kc*32..+31] -> Wst[n][0..15], vectorized ----
#pragma unroll
        for (int it = 0; it < 2; it++) {
            int idx = it * 256 + tid;          // 0..511 uint4s
            int n = idx >> 2, j4 = idx & 3;
            uint4 u = *(const uint4*)&Wtb[n * DD + kc * 32 + j4 * 8];
            *(uint4*)&Wst[n][j4 * 4] = u;
        }
        __syncthreads();

#pragma unroll
        for (int ks = 0; ks < 2; ks++) {       // two k16 steps per kc
            const int o0 = ks * 8 + tig;
            const int o1 = o0 + 4;
            unsigned a[2][4], bf[8][2];
#pragma unroll
            for (int mt = 0; mt < 2; mt++) {
                int mr = wm * 32 + mt * 16 + gid;
                a[mt][0] = Xs[mr][o0];
                a[mt][1] = Xs[mr + 8][o0];
                a[mt][2] = Xs[mr][o1];
                a[mt][3] = Xs[mr + 8][o1];
            }
#pragma unroll
            for (int nt = 0; nt < 8; nt++) {
                int nc = wn * 64 + nt * 8 + gid;
                bf[nt][0] = Wst[nc][o0];
                bf[nt][1] = Wst[nc][o1];
            }
#pragma unroll
            for (int mt = 0; mt < 2; mt++)
#pragma unroll
                for (int nt = 0; nt < 8; nt++)
                    mma_f16(c[mt][nt], a[mt], bf[nt]);
        }
        __syncthreads();
    }

#pragma unroll
    for (int mt = 0; mt < 2; mt++) {
        int row0 = bm + wm * 32 + mt * 16 + gid;
        int row1 = row0 + 8;
#pragma unroll
        for (int nt = 0; nt < 8; nt++) {
            int col = b * 128 + wn * 64 + nt * 8 + 2 * tig;
            if (row0 < NN)
                *(__half2*)&g_hb_h[row0 * BH + col] = __floats2half2_rn(c[mt][nt][0], c[mt][nt][1]);
            if (row1 < NN)
                *(__half2*)&g_hb_h[row1 * BH + col] = __floats2half2_rn(c[mt][nt][2], c[mt][nt][3]);
        }
    }
}

// ---------------- sorted-run scatter: warp per 8 dst-sorted edges ----------------
__device__ __forceinline__ float4 edge_msg(int s, int t, const float* __restrict__ comp, int lane) {
    float4 cf = __ldg((const float4*)&comp[t * BB]);
    const uint2* hb = (const uint2*)&g_hb_h[(size_t)s * BH];
    uint2 u0 = hb[lane];
    uint2 u1 = hb[32 + lane];
    uint2 u2 = hb[64 + lane];
    uint2 u3 = hb[96 + lane];
    float2 a0 = __half22float2(*(const __half2*)&u0.x);
    float2 b0 = __half22float2(*(const __half2*)&u0.y);
    float2 a1 = __half22float2(*(const __half2*)&u1.x);
    float2 b1 = __half22float2(*(const __half2*)&u1.y);
    float2 a2 = __half22float2(*(const __half2*)&u2.x);
    float2 b2 = __half22float2(*(const __half2*)&u2.y);
    float2 a3 = __half22float2(*(const __half2*)&u3.x);
    float2 b3 = __half22float2(*(const __half2*)&u3.y);
    float4 m;
    m.x = cf.x * a0.x + cf.y * a1.x + cf.z * a2.x + cf.w * a3.x;
    m.y = cf.x * a0.y + cf.y * a1.y + cf.z * a2.y + cf.w * a3.y;
    m.z = cf.x * b0.x + cf.y * b1.x + cf.z * b2.x + cf.w * b3.x;
    m.w = cf.x * b0.y + cf.y * b1.y + cf.z * b2.y + cf.w * b3.y;
    return m;
}

__device__ __forceinline__ void red4(float* p, float4 v) {
    asm volatile("red.global.add.v4.f32 [%0], {%1,%2,%3,%4};"
                 :: "l"(p), "f"(v.x), "f"(v.y), "f"(v.z), "f"(v.w) : "memory");
}

__global__ __launch_bounds__(256) void k_scatter(const float* __restrict__ comp) {
    int w = (blockIdx.x * blockDim.x + threadIdx.x) >> 5;   // warp id = 8-edge window
    int lane = threadIdx.x & 31;
    int base = w * 8;
    if (base >= EE) return;

    int4 s03 = *(const int4*)&g_ssrc[base];
    int4 s47 = *(const int4*)&g_ssrc[base + 4];
    int4 d03 = *(const int4*)&g_sdst[base];
    int4 d47 = *(const int4*)&g_sdst[base + 4];
    int4 t03 = *(const int4*)&g_set[base];
    int4 t47 = *(const int4*)&g_set[base + 4];
    int s[8] = {s03.x, s03.y, s03.z, s03.w, s47.x, s47.y, s47.z, s47.w};
    int d[8] = {d03.x, d03.y, d03.z, d03.w, d47.x, d47.y, d47.z, d47.w};
    int t[8] = {t03.x, t03.y, t03.z, t03.w, t47.x, t47.y, t47.z, t47.w};

    float4 acc = edge_msg(s[0], t[0], comp, lane);
#pragma unroll
    for (int j = 1; j < 8; j++) {
        float4 m = edge_msg(s[j], t[j], comp, lane);
        if (d[j] == d[j - 1]) {
            acc.x += m.x; acc.y += m.y; acc.z += m.z; acc.w += m.w;
        } else {
            red4(&g_agg[d[j - 1] * DD + lane * 4], acc);
            acc = m;
        }
    }
    red4(&g_agg[d[7] * DD + lane * 4], acc);
}

// ---------------- x = [relu](agg / deg + bias), reset agg (float4) ----------------
__global__ void k_finish(const float* __restrict__ bias, int do_relu) {
    int i = blockIdx.x * blockDim.x + threadIdx.x;
    if (i < NN * DD / 4) {
        int n = i >> 5;
        float inv = 1.0f / fmaxf((float)g_deg[n], 1.0f);
        float4 v = *(const float4*)&g_agg[i * 4];
        float4 bsv = *(const float4*)&bias[(i & 31) * 4];
        v.x = v.x * inv + bsv.x;
        v.y = v.y * inv + bsv.y;
        v.z = v.z * inv + bsv.z;
        v.w = v.w * inv + bsv.w;
        if (do_relu) {
            v.x = fmaxf(v.x, 0.f); v.y = fmaxf(v.y, 0.f);
            v.z = fmaxf(v.z, 0.f); v.w = fmaxf(v.w, 0.f);
        }
        *(float4*)&g_x[i * 4] = v;
        *(float4*)&g_agg[i * 4] = make_float4(0.f, 0.f, 0.f, 0.f);
    }
}

// ---------------- decode ----------------
__global__ void k_zero_acc() {
    int i = threadIdx.x;
    if (i < 3) g_acc[i] = 0.0;
}

__device__ __forceinline__ float softplusf(float x) {
    return fmaxf(x, 0.f) + log1pf(expf(-fabsf(x)));
}

__global__ __launch_bounds__(256) void k_decode(const int* __restrict__ hh,
                                                const int* __restrict__ tt,
                                                const int* __restrict__ et,
                                                const int* __restrict__ ng,
                                                const float* __restrict__ rel,
                                                float* __restrict__ out) {
    __shared__ float s_lp[8], s_ln[8], s_au[8];
    int w = (blockIdx.x * blockDim.x + threadIdx.x) >> 5;
    int lane = threadIdx.x & 31;
    int wid = threadIdx.x >> 5;
    float lp = 0.f, ln = 0.f, au = 0.f;
    if (w < EE) {
        int a = hh[w], b = tt[w], c = ng[w], r = et[w];
        float4 xh = *(const float4*)&g_x[a * DD + lane * 4];
        float4 xt = *(const float4*)&g_x[b * DD + lane * 4];
        float4 xn = *(const float4*)&g_x[c * DD + lane * 4];
        float4 re = *(const float4*)&rel[r * DD + lane * 4];
        float hx = xh.x * re.x, hy = xh.y * re.y, hz = xh.z * re.z, hw = xh.w * re.w;
        float p = hx * xt.x + hy * xt.y + hz * xt.z + hw * xt.w;
        float q = hx * xn.x + hy * xn.y + hz * xn.z + hw * xn.w;
#pragma unroll
        for (int o = 16; o; o >>= 1) {
            p += __shfl_xor_sync(0xFFFFFFFFu, p, o);
            q += __shfl_xor_sync(0xFFFFFFFFu, q, o);
        }
        if (lane == 0) {
            out[w] = p;
            lp = softplusf(-p);
            ln = softplusf(q);
            au = (p > q) ? 1.f : 0.f;
        }
    }
    if (lane == 0) { s_lp[wid] = lp; s_ln[wid] = ln; s_au[wid] = au; }
    __syncthreads();
    if (threadIdx.x == 0) {
        double A = 0, Bd = 0, C = 0;
#pragma unroll
        for (int k = 0; k < 8; k++) { A += s_lp[k]; Bd += s_ln[k]; C += s_au[k]; }
        atomicAdd(&g_acc[0], A);
        atomicAdd(&g_acc[1], Bd);
        atomicAdd(&g_acc[2], C);
    }
}

__global__ void k_final(float* __restrict__ out, int out_size) {
    if (blockIdx.x == 0 && threadIdx.x == 0) {
        double inv = 1.0 / (double)EE;
        if (out_size >= EE + 1) out[EE] = (float)(0.5 * (g_acc[0] + g_acc[1]) * inv);
        if (out_size >= EE + 2) out[EE + 1] = (float)(g_acc[2] * inv);
    }
}

// ---------------- launch ----------------
extern "C" void kernel_launch(void* const* d_in, const int* in_sizes, int n_in,
                              void* d_out, int out_size) {
    const float* emb    = (const float*)d_in[0];
    const float* ebias  = (const float*)d_in[1];
    const float* bases1 = (const float*)d_in[2];
    const float* comp1  = (const float*)d_in[3];
    const float* bias1  = (const float*)d_in[4];
    const float* bases2 = (const float*)d_in[5];
    const float* comp2  = (const float*)d_in[6];
    const float* bias2  = (const float*)d_in[7];
    const float* rel    = (const float*)d_in[8];
    const int*   eidx   = (const int*)d_in[9];
    const int*   etype  = (const int*)d_in[10];
    const int*   negt   = (const int*)d_in[11];
    const int* src = eidx;
    const int* dst = eidx + EE;
    float* out = (float*)d_out;

    // CSR build (dst-sorted edge arrays) + W transposes + x0
    k_zero_deg<<<(NN + 255) / 256, 256>>>();
    k_count_deg<<<(EE + 255) / 256, 256>>>(dst);
    k_scan<<<1, SCAN_T>>>();
    k_fill<<<(EE + 255) / 256, 256>>>(src, dst, etype);
    k_wt<<<(BB * DD * DD + 255) / 256, 256>>>(bases1, 0);
    k_wt<<<(BB * DD * DD + 255) / 256, 256>>>(bases2, 1);
    k_x0<<<(NN * DD / 4 + 255) / 256, 256>>>(emb, ebias);

    dim3 ggrid(BB, (NN + 127) / 128);   // (4, 391)
    int sc_blocks = (EE / 8 + 7) / 8;   // warp = 8 edges, 8 warps/block -> 5000 blocks

    // ---- layer 1 ----
    k_gemm_mma<<<ggrid, 256>>>(0);
    k_scatter<<<sc_blocks, 256>>>(comp1);
    k_finish<<<(NN * DD / 4 + 255) / 256, 256>>>(bias1, 1);

    // ---- layer 2 ----
    k_gemm_mma<<<ggrid, 256>>>(1);
    k_scatter<<<sc_blocks, 256>>>(comp2);
    k_finish<<<(NN * DD / 4 + 255) / 256, 256>>>(bias2, 0);

    // ---- decode ----
    k_zero_acc<<<1, 32>>>();
    k_decode<<<EE / 8, 256>>>(src, dst, etype, negt, rel, out);
    k_final<<<1, 32>>>(out, out_size);
}

// round 12
// speedup vs baseline: 1.2796x; 1.1312x over previous
#include <cuda_runtime.h>
#include <cuda_fp16.h>
#include <math.h>

#define NN 50000        // num nodes
#define DD 128          // embedding dim (= hidden dim)
#define BB 4            // num bases
#define EE 320000       // num edges
#define BH 512          // BB * DD

// ---------------- static scratch ----------------
__device__ float  g_x[NN * DD];          // node features, 25.6 MB
__device__ __half g_hb_h[NN * BH];       // per-base projections (fp16), 51.2 MB
__device__ float  g_agg[NN * DD];        // scatter accumulator, 25.6 MB
__device__ __half g_Wt[2 * BB * DD * DD];// transposed bases [layer][b][n][k] fp16
__device__ int    g_deg[NN];
__device__ double g_acc[3];              // loss_pos, loss_neg, auc_count

// ---------------- degree ----------------
__global__ void k_zero_deg() {
    int i = blockIdx.x * blockDim.x + threadIdx.x;
    if (i < NN) g_deg[i] = 0;
}
__global__ void k_count_deg(const int* __restrict__ dst) {
    int e = blockIdx.x * blockDim.x + threadIdx.x;
    if (e < EE) atomicAdd(&g_deg[dst[e]], 1);
}

// ---------------- transpose bases -> g_Wt[layer][b][n][k] fp16 ----------------
__global__ void k_wt(const float* __restrict__ bases, int layer) {
    int i = blockIdx.x * blockDim.x + threadIdx.x;   // over 4*128*128
    if (i < BB * DD * DD) {
        int b = i >> 14, k = (i >> 7) & 127, n = i & 127;
        g_Wt[((layer * BB + b) * DD + n) * DD + k] = __float2half(bases[i]);
    }
}

// ---------------- x0 = relu(emb + bias), zero agg (float4) ----------------
__global__ void k_x0(const float* __restrict__ emb, const float* __restrict__ eb) {
    int i = blockIdx.x * blockDim.x + threadIdx.x;
    if (i < NN * DD / 4) {
        float4 v = *(const float4*)&emb[i * 4];
        float4 bsv = *(const float4*)&eb[(i & 31) * 4];
        v.x = fmaxf(v.x + bsv.x, 0.f);
        v.y = fmaxf(v.y + bsv.y, 0.f);
        v.z = fmaxf(v.z + bsv.z, 0.f);
        v.w = fmaxf(v.w + bsv.w, 0.f);
        *(float4*)&g_x[i * 4] = v;
        *(float4*)&g_agg[i * 4] = make_float4(0.f, 0.f, 0.f, 0.f);
    }
}

// ---------------- f16 mma helper ----------------
__device__ __forceinline__ void mma_f16(float c[4], const unsigned a[4], const unsigned b[2]) {
    asm volatile(
        "mma.sync.aligned.m16n8k16.row.col.f32.f16.f16.f32 "
        "{%0,%1,%2,%3}, {%4,%5,%6,%7}, {%8,%9}, {%0,%1,%2,%3};\n"
        : "+f"(c[0]), "+f"(c[1]), "+f"(c[2]), "+f"(c[3])
        : "r"(a[0]), "r"(a[1]), "r"(a[2]), "r"(a[3]), "r"(b[0]), "r"(b[1]));
}

// ---------------- fp16 GEMM: g_hb_h[N,512] = g_x[N,128] @ W[b] ----------------
// Block tile 128(M) x 128(N=one basis) x 32(K). m16n8k16 f16 mma, fp32 accum.
__global__ __launch_bounds__(256, 2) void k_gemm_mma(int layer) {
    __shared__ unsigned Xs[128][20];   // half2 cells [m][k/2], pad 20 -> conflict-free
    __shared__ unsigned Wst[128][20];  // half2 cells [n][k/2]

    const int b  = blockIdx.x;
    const int bm = blockIdx.y * 128;
    const int tid = threadIdx.x;
    const int lane = tid & 31;
    const int wid = tid >> 5;
    const int wm = wid & 3;            // warp row, 32 rows each
    const int wn = wid >> 2;           // warp col, 64 cols each
    const int gid = lane >> 2;         // 0..7
    const int tig = lane & 3;          // 0..3

    const __half* Wtb = &g_Wt[(layer * BB + b) * DD * DD];

    float c[2][8][4];
#pragma unroll
    for (int mt = 0; mt < 2; mt++)
#pragma unroll
        for (int nt = 0; nt < 8; nt++)
#pragma unroll
            for (int i = 0; i < 4; i++) c[mt][nt][i] = 0.f;

#pragma unroll
    for (int kc = 0; kc < 4; kc++) {
        // ---- X tile 128x32 -> half2 ----
#pragma unroll
        for (int it = 0; it < 4; it++) {
            int idx = it * 256 + tid;          // 0..1023 float4s
            int r = idx >> 3, c4 = idx & 7;
            float4 a = make_float4(0.f, 0.f, 0.f, 0.f);
            int grow = bm + r;
            if (grow < NN) a = *(const float4*)&g_x[grow * DD + kc * 32 + c4 * 4];
            __half2 h0 = __floats2half2_rn(a.x, a.y);
            __half2 h1 = __floats2half2_rn(a.z, a.w);
            Xs[r][c4 * 2 + 0] = *(const unsigned*)&h0;
            Xs[r][c4 * 2 + 1] = *(const unsigned*)&h1;
        }
        // ---- W tile: g_Wt[b][n][kc*32..+31] -> Wst[n][0..15], vectorized ----
#pragma unroll
        for (int it = 0; it < 2; it++) {
            int idx = it * 256 + tid;          // 0..511 uint4s
            int n = idx >> 2, j4 = idx & 3;
            uint4 u = *(const uint4*)&Wtb[n * DD + kc * 32 + j4 * 8];
            *(uint4*)&Wst[n][j4 * 4] = u;
        }
        __syncthreads();

#pragma unroll
        for (int ks = 0; ks < 2; ks++) {       // two k16 steps per kc
            const int o0 = ks * 8 + tig;
            const int o1 = o0 + 4;
            unsigned a[2][4], bf[8][2];
#pragma unroll
            for (int mt = 0; mt < 2; mt++) {
                int mr = wm * 32 + mt * 16 + gid;
                a[mt][0] = Xs[mr][o0];
                a[mt][1] = Xs[mr + 8][o0];
                a[mt][2] = Xs[mr][o1];
                a[mt][3] = Xs[mr + 8][o1];
            }
#pragma unroll
            for (int nt = 0; nt < 8; nt++) {
                int nc = wn * 64 + nt * 8 + gid;
                bf[nt][0] = Wst[nc][o0];
                bf[nt][1] = Wst[nc][o1];
            }
#pragma unroll
            for (int mt = 0; mt < 2; mt++)
#pragma unroll
                for (int nt = 0; nt < 8; nt++)
                    mma_f16(c[mt][nt], a[mt], bf[nt]);
        }
        __syncthreads();
    }

#pragma unroll
    for (int mt = 0; mt < 2; mt++) {
        int row0 = bm + wm * 32 + mt * 16 + gid;
        int row1 = row0 + 8;
#pragma unroll
        for (int nt = 0; nt < 8; nt++) {
            int col = b * 128 + wn * 64 + nt * 8 + 2 * tig;
            if (row0 < NN)
                *(__half2*)&g_hb_h[row0 * BH + col] = __floats2half2_rn(c[mt][nt][0], c[mt][nt][1]);
            if (row1 < NN)
                *(__half2*)&g_hb_h[row1 * BH + col] = __floats2half2_rn(c[mt][nt][2], c[mt][nt][3]);
        }
    }
}

// ---------------- per-edge message + scatter-add: one warp per edge (R5 structure) ----------------
__global__ __launch_bounds__(256) void k_scatter(const int* __restrict__ src,
                                                 const int* __restrict__ dst,
                                                 const int* __restrict__ et,
                                                 const float* __restrict__ comp) {
    int w = (blockIdx.x * blockDim.x + threadIdx.x) >> 5;
    int lane = threadIdx.x & 31;
    if (w >= EE) return;
    int s = src[w], d = dst[w], t = et[w];
    float4 cf = __ldg((const float4*)&comp[t * BB]);
    const uint2* hb = (const uint2*)&g_hb_h[(size_t)s * BH];
    uint2 u0 = hb[lane];
    uint2 u1 = hb[32 + lane];
    uint2 u2 = hb[64 + lane];
    uint2 u3 = hb[96 + lane];
    float2 a0 = __half22float2(*(const __half2*)&u0.x);
    float2 b0 = __half22float2(*(const __half2*)&u0.y);
    float2 a1 = __half22float2(*(const __half2*)&u1.x);
    float2 b1 = __half22float2(*(const __half2*)&u1.y);
    float2 a2 = __half22float2(*(const __half2*)&u2.x);
    float2 b2 = __half22float2(*(const __half2*)&u2.y);
    float2 a3 = __half22float2(*(const __half2*)&u3.x);
    float2 b3 = __half22float2(*(const __half2*)&u3.y);
    float4 m;
    m.x = cf.x * a0.x + cf.y * a1.x + cf.z * a2.x + cf.w * a3.x;
    m.y = cf.x * a0.y + cf.y * a1.y + cf.z * a2.y + cf.w * a3.y;
    m.z = cf.x * b0.x + cf.y * b1.x + cf.z * b2.x + cf.w * b3.x;
    m.w = cf.x * b0.y + cf.y * b1.y + cf.z * b2.y + cf.w * b3.y;
    float* p = &g_agg[d * DD + lane * 4];
    asm volatile("red.global.add.v4.f32 [%0], {%1,%2,%3,%4};"
                 :: "l"(p), "f"(m.x), "f"(m.y), "f"(m.z), "f"(m.w) : "memory");
}

// ---------------- x = [relu](agg / deg + bias), reset agg (float4) ----------------
__global__ void k_finish(const float* __restrict__ bias, int do_relu) {
    int i = blockIdx.x * blockDim.x + threadIdx.x;
    if (i < NN * DD / 4) {
        int n = i >> 5;
        float inv = 1.0f / fmaxf((float)g_deg[n], 1.0f);
        float4 v = *(const float4*)&g_agg[i * 4];
        float4 bsv = *(const float4*)&bias[(i & 31) * 4];
        v.x = v.x * inv + bsv.x;
        v.y = v.y * inv + bsv.y;
        v.z = v.z * inv + bsv.z;
        v.w = v.w * inv + bsv.w;
        if (do_relu) {
            v.x = fmaxf(v.x, 0.f); v.y = fmaxf(v.y, 0.f);
            v.z = fmaxf(v.z, 0.f); v.w = fmaxf(v.w, 0.f);
        }
        *(float4*)&g_x[i * 4] = v;
        *(float4*)&g_agg[i * 4] = make_float4(0.f, 0.f, 0.f, 0.f);
    }
}

// ---------------- decode ----------------
__global__ void k_zero_acc() {
    int i = threadIdx.x;
    if (i < 3) g_acc[i] = 0.0;
}

__device__ __forceinline__ float softplusf(float x) {
    return fmaxf(x, 0.f) + log1pf(expf(-fabsf(x)));
}

__global__ __launch_bounds__(256) void k_decode(const int* __restrict__ hh,
                                                const int* __restrict__ tt,
                                                const int* __restrict__ et,
                                                const int* __restrict__ ng,
                                                const float* __restrict__ rel,
                                                float* __restrict__ out) {
    __shared__ float s_lp[8], s_ln[8], s_au[8];
    int w = (blockIdx.x * blockDim.x + threadIdx.x) >> 5;
    int lane = threadIdx.x & 31;
    int wid = threadIdx.x >> 5;
    float lp = 0.f, ln = 0.f, au = 0.f;
    if (w < EE) {
        int a = hh[w], b = tt[w], c = ng[w], r = et[w];
        float4 xh = *(const float4*)&g_x[a * DD + lane * 4];
        float4 xt = *(const float4*)&g_x[b * DD + lane * 4];
        float4 xn = *(const float4*)&g_x[c * DD + lane * 4];
        float4 re = *(const float4*)&rel[r * DD + lane * 4];
        float hx = xh.x * re.x, hy = xh.y * re.y, hz = xh.z * re.z, hw = xh.w * re.w;
        float p = hx * xt.x + hy * xt.y + hz * xt.z + hw * xt.w;
        float q = hx * xn.x + hy * xn.y + hz * xn.z + hw * xn.w;
#pragma unroll
        for (int o = 16; o; o >>= 1) {
            p += __shfl_xor_sync(0xFFFFFFFFu, p, o);
            q += __shfl_xor_sync(0xFFFFFFFFu, q, o);
        }
        if (lane == 0) {
            out[w] = p;
            lp = softplusf(-p);
            ln = softplusf(q);
            au = (p > q) ? 1.f : 0.f;
        }
    }
    if (lane == 0) { s_lp[wid] = lp; s_ln[wid] = ln; s_au[wid] = au; }
    __syncthreads();
    if (threadIdx.x == 0) {
        double A = 0, Bd = 0, C = 0;
#pragma unroll
        for (int k = 0; k < 8; k++) { A += s_lp[k]; Bd += s_ln[k]; C += s_au[k]; }
        atomicAdd(&g_acc[0], A);
        atomicAdd(&g_acc[1], Bd);
        atomicAdd(&g_acc[2], C);
    }
}

__global__ void k_final(float* __restrict__ out, int out_size) {
    if (blockIdx.x == 0 && threadIdx.x == 0) {
        double inv = 1.0 / (double)EE;
        if (out_size >= EE + 1) out[EE] = (float)(0.5 * (g_acc[0] + g_acc[1]) * inv);
        if (out_size >= EE + 2) out[EE + 1] = (float)(g_acc[2] * inv);
    }
}

// ---------------- launch ----------------
extern "C" void kernel_launch(void* const* d_in, const int* in_sizes, int n_in,
                              void* d_out, int out_size) {
    const float* emb    = (const float*)d_in[0];
    const float* ebias  = (const float*)d_in[1];
    const float* bases1 = (const float*)d_in[2];
    const float* comp1  = (const float*)d_in[3];
    const float* bias1  = (const float*)d_in[4];
    const float* bases2 = (const float*)d_in[5];
    const float* comp2  = (const float*)d_in[6];
    const float* bias2  = (const float*)d_in[7];
    const float* rel    = (const float*)d_in[8];
    const int*   eidx   = (const int*)d_in[9];
    const int*   etype  = (const int*)d_in[10];
    const int*   negt   = (const int*)d_in[11];
    const int* src = eidx;
    const int* dst = eidx + EE;
    float* out = (float*)d_out;

    // degree + W transposes + x0
    k_zero_deg<<<(NN + 255) / 256, 256>>>();
    k_count_deg<<<(EE + 255) / 256, 256>>>(dst);
    k_wt<<<(BB * DD * DD + 255) / 256, 256>>>(bases1, 0);
    k_wt<<<(BB * DD * DD + 255) / 256, 256>>>(bases2, 1);
    k_x0<<<(NN * DD / 4 + 255) / 256, 256>>>(emb, ebias);

    dim3 ggrid(BB, (NN + 127) / 128);   // (4, 391)

    // ---- layer 1 ----
    k_gemm_mma<<<ggrid, 256>>>(0);
    k_scatter<<<EE / 8, 256>>>(src, dst, etype, comp1);
    k_finish<<<(NN * DD / 4 + 255) / 256, 256>>>(bias1, 1);

    // ---- layer 2 ----
    k_gemm_mma<<<ggrid, 256>>>(1);
    k_scatter<<<EE / 8, 256>>>(src, dst, etype, comp2);
    k_finish<<<(NN * DD / 4 + 255) / 256, 256>>>(bias2, 0);

    // ---- decode ----
    k_zero_acc<<<1, 32>>>();
    k_decode<<<EE / 8, 256>>>(src, dst, etype, negt, rel, out);
    k_final<<<1, 32>>>(out, out_size);
}